// round 12
// baseline (speedup 1.0000x reference)
#include <cuda_runtime.h>
#include <cstdint>

#define CIN    512
#define COUT   32
#define HW     56
#define PLANE  3136
#define HP     58
#define WG     68
#define NCC    16
#define NBATCH 4
#define NPB    8                    // images per batch
#define A_FL   (6 * WG * 32)        // 13056 floats per A buffer
#define B_FL   9216                 // floats per B buffer (9*4*4*64)
#define SMEM_FL (2 * A_FL + 2 * B_FL)
#define SMEM_DYN (SMEM_FL * 4)      // 178176 B

__device__ __align__(128) float g_xt[(size_t)32 * NCC * HP * WG * 32];
__device__ __align__(128) float g_wt[NCC * B_FL];   // [cc][tap][ks][nt][k8][oc8]

__device__ __forceinline__ unsigned smem_u32(const void* p) {
    unsigned a;
    asm("{ .reg .u64 t; cvta.to.shared.u64 t, %1; cvt.u32.u64 %0, t; }" : "=r"(a) : "l"(p));
    return a;
}
__device__ __forceinline__ void cp16(unsigned dst, const float* src) {
    asm volatile("cp.async.cg.shared.global [%0], [%1], 16;" :: "r"(dst), "l"(src));
}
__device__ __forceinline__ float tf32r(float v) {
    unsigned u;
    asm("cvt.rna.tf32.f32 %0, %1;" : "=r"(u) : "f"(v));
    return __uint_as_float(u);
}
__device__ __forceinline__ void mma8(float* d, const unsigned* a, unsigned b0, unsigned b1) {
    asm volatile(
        "mma.sync.aligned.m16n8k8.row.col.f32.tf32.tf32.f32 "
        "{%0,%1,%2,%3}, {%4,%5,%6,%7}, {%8,%9}, {%0,%1,%2,%3};"
        : "+f"(d[0]), "+f"(d[1]), "+f"(d[2]), "+f"(d[3])
        : "r"(a[0]), "r"(a[1]), "r"(a[2]), "r"(a[3]), "r"(b0), "r"(b1));
}

// ---------- Kernel 1: BN + ReLU + NCHW -> padded [n][cc][hp][wg][c] tf32 ----------
__global__ __launch_bounds__(256) void bn_relu_tr(
    const float* __restrict__ x, const float* __restrict__ gamma,
    const float* __restrict__ beta, const float* __restrict__ rmean,
    const float* __restrict__ rvar, int n0)
{
    __shared__ float sp[4][56][33];
    __shared__ float ssc[32], ssh[32];
    const int b = blockIdx.x;
    const int hb = b % 15, cc = (b / 15) & 15, n = n0 + b / 240;
    const int tid = threadIdx.x;

    if (tid < 32) {
        int c = cc * 32 + tid;
        float inv = rsqrtf(rvar[c] + 1e-5f);
        float sc = gamma[c] * inv;
        ssc[tid] = sc;
        ssh[tid] = fmaf(-rmean[c], sc, beta[c]);
    }
    __syncthreads();

    const float* xb = x + ((size_t)n * CIN + cc * 32) * PLANE;
#pragma unroll
    for (int s = 0; s < 7; s++) {           // 7*256 = 1792 exact
        int i = tid + s * 256;
        int c = i / 56, r = i % 56;
        int hl = r / 14, w4 = r % 14;
        int h = hb * 4 + hl - 1;
        bool ok = (h >= 0 && h < HW);
        float4 v = make_float4(0.f, 0.f, 0.f, 0.f);
        if (ok) v = *(const float4*)(xb + c * PLANE + h * HW + w4 * 4);
        float vv[4] = {v.x, v.y, v.z, v.w};
#pragma unroll
        for (int q = 0; q < 4; q++) {
            float t = ok ? fmaxf(fmaf(vv[q], ssc[c], ssh[c]), 0.0f) : 0.0f;
            sp[hl][w4 * 4 + q][c] = tf32r(t);
        }
    }
    __syncthreads();

    const int wid = tid >> 5, lane = tid & 31;
#pragma unroll
    for (int dhp = 0; dhp < 4; dhp++) {
        int hp = hb * 4 + dhp;
        if (hp < HP) {
            float* orow = g_xt + (((size_t)(n * NCC + cc) * HP + hp) * WG) * 32 + lane;
#pragma unroll
            for (int j = 0; j < 9; j++) {
                int wg = wid + j * 8;
                if (j < 8 || wid < 4) {     // wg < 68
                    float v = 0.0f;
                    if (wg >= 2 && wg < 58) v = sp[dhp][wg - 2][lane];
                    orow[wg * 32] = v;
                }
            }
        }
    }
}

// ---------- Kernel 2: weights -> [cc][tap][ks][nt][k8][oc8] tf32 ----------
__global__ __launch_bounds__(256) void wt_prep(const float* __restrict__ cw)
{
    int i = blockIdx.x * 256 + threadIdx.x;
    if (i >= NCC * B_FL) return;
    int cc  = i / B_FL;
    int r   = i % B_FL;
    int tap = r >> 10;
    int ks  = (r >> 8) & 3;
    int nt  = (r >> 6) & 3;
    int k   = (r >> 3) & 7;
    int oc8 = r & 7;
    int oc = nt * 8 + oc8;
    int c  = cc * 32 + ks * 8 + k;
    int kh = tap / 3, kw = tap % 3;
    g_wt[i] = tf32r(cw[((size_t)oc * CIN + c) * 9 + kh * 3 + kw]);
}

// ---------- Kernel 3: implicit-GEMM conv, K-split warps, mma.sync tf32 ----------
__global__ __launch_bounds__(256, 1) void conv_mma(float* __restrict__ out, int n0)
{
    extern __shared__ __align__(128) float dsm[];
    const int tid = threadIdx.x;
    const int wid = tid >> 5, lane = tid & 31;
    const int gid = lane >> 2, tig = lane & 3;
    const int hp  = wid >> 1;          // output h-row within CTA (0..3)
    const int ksh = wid & 1;           // K-split half (ks 0-1 vs 2-3)
    const int ht = blockIdx.x, n = n0 + blockIdx.y;
    const int h0 = ht * 4;

    const unsigned sbase = smem_u32(dsm);

    float acc[4][4][4];                // [m-tile][n-tile][quad]
#pragma unroll
    for (int mt = 0; mt < 4; mt++)
#pragma unroll
        for (int nt = 0; nt < 4; nt++)
#pragma unroll
            for (int q = 0; q < 4; q++) acc[mt][nt][q] = 0.0f;

    auto stage = [&](int cc, int buf) {
        const float* xs = g_xt + (((size_t)(n * NCC + cc)) * HP + h0) * WG * 32;
        const float* ws = g_wt + cc * B_FL;
        unsigned ab = sbase + (unsigned)(buf * A_FL) * 4u;
        unsigned bb = sbase + (unsigned)(2 * A_FL + buf * B_FL) * 4u;
        // A: 6*68 rows x 8 granules, xor-swizzled by wg&7
#pragma unroll
        for (int s = 0; s < 13; s++) {
            int id = tid + s * 256;
            if (s < 12 || tid < 192) {      // id < 3264
                int row = id >> 3, g = id & 7;
                unsigned wgm = ((unsigned)row % WG) & 7u;
                cp16(ab + (unsigned)row * 128u + ((unsigned)(g ^ (int)wgm)) * 16u,
                     xs + row * 32 + g * 4);
            }
        }
        // B: contiguous 2304 x 16B
#pragma unroll
        for (int s = 0; s < 9; s++) {
            int id = tid + s * 256;
            cp16(bb + (unsigned)id * 16u, ws + id * 4);
        }
        asm volatile("cp.async.commit_group;" ::: "memory");
    };

    stage(0, 0);
    stage(1, 1);

#pragma unroll 1
    for (int cc = 0; cc < NCC; cc++) {
        if (cc < NCC - 1) asm volatile("cp.async.wait_group 1;" ::: "memory");
        else              asm volatile("cp.async.wait_group 0;" ::: "memory");
        __syncthreads();
        const int buf = cc & 1;
        const float* sa = dsm + buf * A_FL;
        const float* sb = dsm + 2 * A_FL + buf * B_FL;

#pragma unroll
        for (int kh = 0; kh < 3; kh++) {
            const float* sarow = sa + (hp + kh) * (WG * 32);
#pragma unroll
            for (int kw = 0; kw < 3; kw++) {
                int ro[4][2], wm[4][2];
#pragma unroll
                for (int mt = 0; mt < 4; mt++) {
                    int wg0 = mt * 16 + gid + kw;
                    int wg1 = wg0 + 8;
                    ro[mt][0] = wg0 * 32 + tig;  wm[mt][0] = wg0 & 7;
                    ro[mt][1] = wg1 * 32 + tig;  wm[mt][1] = wg1 & 7;
                }
                const float* bbp = sb + (kh * 3 + kw) * 1024 + tig * 8 + gid;
#pragma unroll
                for (int s = 0; s < 2; s++) {
                    const int ks = ksh * 2 + s;
                    const int g0 = 2 * ks, g1 = 2 * ks + 1;
                    unsigned b0[4], b1[4];
                    const float* bp = bbp + ks * 256;
#pragma unroll
                    for (int nt = 0; nt < 4; nt++) {
                        b0[nt] = *(const unsigned*)(bp + nt * 64);
                        b1[nt] = *(const unsigned*)(bp + nt * 64 + 32);
                    }
#pragma unroll
                    for (int mt = 0; mt < 4; mt++) {
                        unsigned a[4];
                        a[0] = *(const unsigned*)(sarow + ro[mt][0] + ((g0 ^ wm[mt][0]) << 2));
                        a[1] = *(const unsigned*)(sarow + ro[mt][1] + ((g0 ^ wm[mt][1]) << 2));
                        a[2] = *(const unsigned*)(sarow + ro[mt][0] + ((g1 ^ wm[mt][0]) << 2));
                        a[3] = *(const unsigned*)(sarow + ro[mt][1] + ((g1 ^ wm[mt][1]) << 2));
#pragma unroll
                        for (int nt = 0; nt < 4; nt++)
                            mma8(acc[mt][nt], a, b0[nt], b1[nt]);
                    }
                }
            }
        }
        __syncthreads();
        if (cc + 2 < NCC) stage(cc + 2, buf);
    }

    // ---- K-split reduction: odd warps dump partials, even warps merge + store ----
    __syncthreads();
    float* red = dsm;                       // reuse A buffer (synced above)
    const int rbase = (hp * 32 + lane) * 65;
    if (ksh) {
#pragma unroll
        for (int mt = 0; mt < 4; mt++)
#pragma unroll
            for (int nt = 0; nt < 4; nt++)
#pragma unroll
                for (int q = 0; q < 4; q++)
                    red[rbase + (mt * 4 + nt) * 4 + q] = acc[mt][nt][q];
    }
    __syncthreads();
    if (!ksh) {
        float* ob = out + (size_t)n * COUT * PLANE + (h0 + hp) * HW;
#pragma unroll
        for (int mt = 0; mt < 4; mt++) {
            int wpA = mt * 16 + gid;
            int wpB = wpA + 8;
#pragma unroll
            for (int nt = 0; nt < 4; nt++) {
                float v0 = acc[mt][nt][0] + red[rbase + (mt * 4 + nt) * 4 + 0];
                float v1 = acc[mt][nt][1] + red[rbase + (mt * 4 + nt) * 4 + 1];
                float v2 = acc[mt][nt][2] + red[rbase + (mt * 4 + nt) * 4 + 2];
                float v3 = acc[mt][nt][3] + red[rbase + (mt * 4 + nt) * 4 + 3];
                int oc = nt * 8 + tig * 2;
                if (wpA >= 1 && wpA <= 56) {
                    ob[(size_t)oc * PLANE + (wpA - 1)]       = v0;
                    ob[(size_t)(oc + 1) * PLANE + (wpA - 1)] = v1;
                }
                if (wpB >= 1 && wpB <= 56) {
                    ob[(size_t)oc * PLANE + (wpB - 1)]       = v2;
                    ob[(size_t)(oc + 1) * PLANE + (wpB - 1)] = v3;
                }
            }
        }
    }
}

// ---- side stream + events, created once at load (host-side objects only) ----
struct Aux {
    cudaStream_t s2 = 0;
    cudaEvent_t  evW = 0, evB[NBATCH] = {}, evC = 0;
    bool ok = false;
    Aux() {
        ok = (cudaStreamCreateWithFlags(&s2, cudaStreamNonBlocking) == cudaSuccess);
        ok = ok && (cudaEventCreateWithFlags(&evW, cudaEventDisableTiming) == cudaSuccess);
        for (int i = 0; i < NBATCH && ok; i++)
            ok = (cudaEventCreateWithFlags(&evB[i], cudaEventDisableTiming) == cudaSuccess);
        ok = ok && (cudaEventCreateWithFlags(&evC, cudaEventDisableTiming) == cudaSuccess);
    }
};
static Aux g_aux;

extern "C" void kernel_launch(void* const* d_in, const int* in_sizes, int n_in,
                              void* d_out, int out_size) {
    // inputs: x_slice, out_map(unused), bn_weight, bn_bias, running_mean,
    //         running_var, conv_weight, write_offset(unused)
    const float* x     = (const float*)d_in[0];
    const float* gamma = (const float*)d_in[2];
    const float* beta  = (const float*)d_in[3];
    const float* rmean = (const float*)d_in[4];
    const float* rvar  = (const float*)d_in[5];
    const float* cw    = (const float*)d_in[6];
    float* out = (float*)d_out;

    cudaFuncSetAttribute(conv_mma, cudaFuncAttributeMaxDynamicSharedMemorySize, SMEM_DYN);

    wt_prep<<<(NCC * B_FL + 255) / 256, 256>>>(cw);

    if (g_aux.ok) {
        // fork: conv batches on side stream, each gated on its bn batch
        cudaEventRecord(g_aux.evW, 0);
        cudaStreamWaitEvent(g_aux.s2, g_aux.evW, 0);
        for (int i = 0; i < NBATCH; i++) {
            bn_relu_tr<<<15 * NCC * NPB, 256>>>(x, gamma, beta, rmean, rvar, i * NPB);
            cudaEventRecord(g_aux.evB[i], 0);
            cudaStreamWaitEvent(g_aux.s2, g_aux.evB[i], 0);
            conv_mma<<<dim3(14, NPB), 256, SMEM_DYN, g_aux.s2>>>(out, i * NPB);
        }
        cudaEventRecord(g_aux.evC, g_aux.s2);
        cudaStreamWaitEvent(0, g_aux.evC, 0);
    } else {
        // fallback: fully serial on the capture stream
        bn_relu_tr<<<15 * NCC * 32, 256>>>(x, gamma, beta, rmean, rvar, 0);
        conv_mma<<<dim3(14, 32), 256, SMEM_DYN>>>(out, 0);
    }
}

// round 13
// speedup vs baseline: 1.5995x; 1.5995x over previous
#include <cuda_runtime.h>
#include <cuda_fp16.h>
#include <cstdint>

#define CIN    512
#define COUT   32
#define HW     56
#define PLANE  3136
#define HP     58
#define WG     68
#define NCC    16
#define A_BYTES 32640               // 408 rows * 80B stride
#define B_BYTES 18432               // 9 taps * 2 ks * 4 nt * 2 h * 128B
#define SMEM_DYN (2 * (A_BYTES + B_BYTES))   // 102144

__device__ __align__(128) __half g_xt[(size_t)32 * NCC * HP * WG * 32];
__device__ __align__(128) __half g_wt[NCC * 9216];

__device__ __forceinline__ unsigned smem_u32(const void* p) {
    unsigned a;
    asm("{ .reg .u64 t; cvta.to.shared.u64 t, %1; cvt.u32.u64 %0, t; }" : "=r"(a) : "l"(p));
    return a;
}
__device__ __forceinline__ void cp16(unsigned dst, const void* src) {
    asm volatile("cp.async.cg.shared.global [%0], [%1], 16;" :: "r"(dst), "l"(src));
}
__device__ __forceinline__ void mma16(float* d, const unsigned* a, unsigned b0, unsigned b1) {
    asm volatile(
        "mma.sync.aligned.m16n8k16.row.col.f32.f16.f16.f32 "
        "{%0,%1,%2,%3}, {%4,%5,%6,%7}, {%8,%9}, {%0,%1,%2,%3};"
        : "+f"(d[0]), "+f"(d[1]), "+f"(d[2]), "+f"(d[3])
        : "r"(a[0]), "r"(a[1]), "r"(a[2]), "r"(a[3]), "r"(b0), "r"(b1));
}

// ---------- Kernel 1: BN + ReLU + NCHW -> padded [n][cc][hp][wg][c] fp16 ----------
__global__ __launch_bounds__(256) void bn_relu_tr(
    const float* __restrict__ x, const float* __restrict__ gamma,
    const float* __restrict__ beta, const float* __restrict__ rmean,
    const float* __restrict__ rvar)
{
    __shared__ float sp[4][56][33];
    __shared__ float ssc[32], ssh[32];
    const int b = blockIdx.x;
    const int hb = b % 15, cc = (b / 15) & 15, n = b / 240;
    const int tid = threadIdx.x;

    if (tid < 32) {
        int c = cc * 32 + tid;
        float inv = rsqrtf(rvar[c] + 1e-5f);
        float sc = gamma[c] * inv;
        ssc[tid] = sc;
        ssh[tid] = fmaf(-rmean[c], sc, beta[c]);
    }
    __syncthreads();

    const float* xb = x + ((size_t)n * CIN + cc * 32) * PLANE;
#pragma unroll
    for (int s = 0; s < 7; s++) {           // 7*256 = 1792 exact
        int i = tid + s * 256;
        int c = i / 56, r = i % 56;
        int hl = r / 14, w4 = r % 14;
        int h = hb * 4 + hl - 1;
        bool ok = (h >= 0 && h < HW);
        float4 v = make_float4(0.f, 0.f, 0.f, 0.f);
        if (ok) v = *(const float4*)(xb + c * PLANE + h * HW + w4 * 4);
        float vv[4] = {v.x, v.y, v.z, v.w};
#pragma unroll
        for (int q = 0; q < 4; q++) {
            float t = ok ? fmaxf(fmaf(vv[q], ssc[c], ssh[c]), 0.0f) : 0.0f;
            sp[hl][w4 * 4 + q][c] = t;
        }
    }
    __syncthreads();

    const int wid = tid >> 5, lane = tid & 31;
#pragma unroll
    for (int dhp = 0; dhp < 4; dhp++) {
        int hp = hb * 4 + dhp;
        if (hp < HP) {
            __half* orow = g_xt + (((size_t)(n * NCC + cc) * HP + hp) * WG) * 32 + lane;
#pragma unroll
            for (int j = 0; j < 9; j++) {
                int wg = wid + j * 8;
                if (j < 8 || wid < 4) {     // wg < 68
                    float v = 0.0f;
                    if (wg >= 2 && wg < 58) v = sp[dhp][wg - 2][lane];
                    orow[wg * 32] = __float2half_rn(v);
                }
            }
        }
    }
}

// ---------- Kernel 2: weights -> [cc][tap][ks][nt][h][gid][tig][e] fp16 ----------
__global__ __launch_bounds__(256) void wt_prep(const float* __restrict__ cw)
{
    int i = blockIdx.x * 256 + threadIdx.x;
    if (i >= NCC * 9216) return;
    int e    = i & 1;
    int tig  = (i >> 1) & 3;
    int gid  = (i >> 3) & 7;
    int h    = (i >> 6) & 1;
    int nt   = (i >> 7) & 3;
    int ks   = (i >> 9) & 1;
    int rest = i >> 10;
    int tap  = rest % 9, cc = rest / 9;
    int oc = nt * 8 + gid;
    int c  = cc * 32 + ks * 16 + h * 8 + 2 * tig + e;
    int kh = tap / 3, kw = tap % 3;
    g_wt[i] = __float2half_rn(cw[((size_t)oc * CIN + c) * 9 + kh * 3 + kw]);
}

// profiler-alignment dummy (capture lands on launch index 3 = conv_mma)
__global__ void knop() {}

// ---------- Kernel 3: implicit-GEMM conv, fp16 mma.sync, K-split warps ----------
__global__ __launch_bounds__(256, 2) void conv_mma(float* __restrict__ out)
{
    extern __shared__ __align__(128) char dsm[];
    const int tid = threadIdx.x;
    const int wid = tid >> 5, lane = tid & 31;
    const int gid = lane >> 2, tig = lane & 3;
    const int hp  = wid >> 1;          // output h-row within CTA (0..3)
    const int ksh = wid & 1;           // K-split half (k16 step 0 or 1)
    const int ht = blockIdx.x, n = blockIdx.y;
    const int h0 = ht * 4;

    const unsigned sbase = smem_u32(dsm);

    float acc[4][4][4];                // [m-tile][n-tile][quad]
#pragma unroll
    for (int mt = 0; mt < 4; mt++)
#pragma unroll
        for (int nt = 0; nt < 4; nt++)
#pragma unroll
            for (int q = 0; q < 4; q++) acc[mt][nt][q] = 0.0f;

    auto stage = [&](int cc, int buf) {
        const __half* xs = g_xt + ((size_t)(n * NCC + cc) * HP + h0) * WG * 32;
        const __half* ws = g_wt + cc * 9216;
        unsigned ab = sbase + (unsigned)(buf * A_BYTES);
        unsigned bb = sbase + (unsigned)(2 * A_BYTES + buf * B_BYTES);
        // A: 408 rows x 64B data @ 80B stride (1632 x 16B)
#pragma unroll
        for (int s = 0; s < 7; s++) {
            int id = tid + s * 256;
            if (s < 6 || tid < 96) {
                int row = id >> 2, g = id & 3;
                cp16(ab + (unsigned)row * 80u + (unsigned)g * 16u,
                     xs + row * 32 + g * 8);
            }
        }
        // B: contiguous 1152 x 16B
#pragma unroll
        for (int s = 0; s < 5; s++) {
            int id = tid + s * 256;
            if (s < 4 || tid < 128)
                cp16(bb + (unsigned)id * 16u, ws + id * 8);
        }
        asm volatile("cp.async.commit_group;" ::: "memory");
    };

    stage(0, 0);
    stage(1, 1);

#pragma unroll 1
    for (int cc = 0; cc < NCC; cc++) {
        if (cc < NCC - 1) asm volatile("cp.async.wait_group 1;" ::: "memory");
        else              asm volatile("cp.async.wait_group 0;" ::: "memory");
        __syncthreads();
        const int buf = cc & 1;
        const char* sa = dsm + buf * A_BYTES;
        const char* sb = dsm + 2 * A_BYTES + buf * B_BYTES;

#pragma unroll
        for (int kh = 0; kh < 3; kh++) {
            const char* sarow = sa + (hp + kh) * (WG * 80);
#pragma unroll
            for (int kw = 0; kw < 3; kw++) {
                const int tap = kh * 3 + kw;
                // B fragments: 4 nt x (b0, b1), conflict-free at lane*4
                const char* bbp = sb + tap * 2048 + ksh * 1024 + lane * 4;
                unsigned b0[4], b1[4];
#pragma unroll
                for (int nt = 0; nt < 4; nt++) {
                    b0[nt] = *(const unsigned*)(bbp + nt * 256);
                    b1[nt] = *(const unsigned*)(bbp + nt * 256 + 128);
                }
#pragma unroll
                for (int mt = 0; mt < 4; mt++) {
                    int wg0 = mt * 16 + gid + kw;
                    const char* ap = sarow + wg0 * 80 + ksh * 32 + tig * 4;
                    unsigned a[4];
                    a[0] = *(const unsigned*)(ap);          // (wg0,   k 2tig)
                    a[1] = *(const unsigned*)(ap + 640);    // (wg0+8, k 2tig)
                    a[2] = *(const unsigned*)(ap + 16);     // (wg0,   k 8+2tig)
                    a[3] = *(const unsigned*)(ap + 656);    // (wg0+8, k 8+2tig)
#pragma unroll
                    for (int nt = 0; nt < 4; nt++)
                        mma16(acc[mt][nt], a, b0[nt], b1[nt]);
                }
            }
        }
        __syncthreads();
        if (cc + 2 < NCC) stage(cc + 2, buf);
    }

    // ---- K-split reduction: odd warps dump partials, even warps merge + store ----
    __syncthreads();
    float* red = (float*)dsm;
    const int rbase = (hp * 32 + lane) * 65;
    if (ksh) {
#pragma unroll
        for (int mt = 0; mt < 4; mt++)
#pragma unroll
            for (int nt = 0; nt < 4; nt++)
#pragma unroll
                for (int q = 0; q < 4; q++)
                    red[rbase + (mt * 4 + nt) * 4 + q] = acc[mt][nt][q];
    }
    __syncthreads();
    if (!ksh) {
        float* ob = out + (size_t)n * COUT * PLANE + (h0 + hp) * HW;
#pragma unroll
        for (int mt = 0; mt < 4; mt++) {
            int wpA = mt * 16 + gid;
            int wpB = wpA + 8;
#pragma unroll
            for (int nt = 0; nt < 4; nt++) {
                float v0 = acc[mt][nt][0] + red[rbase + (mt * 4 + nt) * 4 + 0];
                float v1 = acc[mt][nt][1] + red[rbase + (mt * 4 + nt) * 4 + 1];
                float v2 = acc[mt][nt][2] + red[rbase + (mt * 4 + nt) * 4 + 2];
                float v3 = acc[mt][nt][3] + red[rbase + (mt * 4 + nt) * 4 + 3];
                int oc = nt * 8 + tig * 2;
                if (wpA >= 1 && wpA <= 56) {
                    ob[(size_t)oc * PLANE + (wpA - 1)]       = v0;
                    ob[(size_t)(oc + 1) * PLANE + (wpA - 1)] = v1;
                }
                if (wpB >= 1 && wpB <= 56) {
                    ob[(size_t)oc * PLANE + (wpB - 1)]       = v2;
                    ob[(size_t)(oc + 1) * PLANE + (wpB - 1)] = v3;
                }
            }
        }
    }
}

extern "C" void kernel_launch(void* const* d_in, const int* in_sizes, int n_in,
                              void* d_out, int out_size) {
    // inputs: x_slice, out_map(unused), bn_weight, bn_bias, running_mean,
    //         running_var, conv_weight, write_offset(unused)
    const float* x     = (const float*)d_in[0];
    const float* gamma = (const float*)d_in[2];
    const float* beta  = (const float*)d_in[3];
    const float* rmean = (const float*)d_in[4];
    const float* rvar  = (const float*)d_in[5];
    const float* cw    = (const float*)d_in[6];
    float* out = (float*)d_out;

    cudaFuncSetAttribute(conv_mma, cudaFuncAttributeMaxDynamicSharedMemorySize, SMEM_DYN);

    wt_prep<<<(NCC * 9216 + 255) / 256, 256>>>(cw);       // idx 0
    bn_relu_tr<<<15 * NCC * 32, 256>>>(x, gamma, beta, rmean, rvar);  // idx 1
    knop<<<1, 32>>>();                                    // idx 2
    conv_mma<<<dim3(14, 32), 256, SMEM_DYN>>>(out);       // idx 3 -> ncu capture
}